// round 6
// baseline (speedup 1.0000x reference)
#include <cuda_runtime.h>
#include <math.h>

#define NB 8192                 // batch rows
#define ND 1024                 // feature dim
#define NG 8                    // tile count
#define TOTAL (NB * ND)         // 8,388,608 floats
#define BLOCKS 1024
#define THREADS 128
#define ROWS_PB (NB / BLOCKS)   // 8 rows per block
#define F4_ROW (ND / 4)         // 256 float4 per row

__device__ float g_partials[BLOCKS];
__device__ float g_mean;
__device__ float g_scale;
__device__ unsigned int g_ticket = 0;   // reset by last block each launch
__device__ unsigned int g_flag = 0;     // monotone generation counter

__global__ void __launch_bounds__(THREADS, 8) k_fused(
    const float4* __restrict__ x4, const float* __restrict__ wp,
    float4* __restrict__ out4) {
    __shared__ float s_w[THREADS / 32];
    __shared__ float s_ss[ROWS_PB][THREADS / 32];
    __shared__ float s_inv[ROWS_PB];
    __shared__ float s_ms[2];
    __shared__ bool  s_last;

    int tid = threadIdx.x;
    int wid = tid >> 5, lid = tid & 31;
    int b = blockIdx.x;

    // epoch read precedes this block's ticket; the increment requires ALL
    // tickets, so either we read the stale value (spin until bump) or the
    // bumped value (mean already published) — both safe.
    unsigned int epoch = *(volatile unsigned int*)&g_flag;

    const float4* xblk = x4 + (long long)b * (ROWS_PB * F4_ROW);

    // ---- phase 1: sum this block's 8 rows (32 KB, coalesced, MLP=16) ----
    float s = 0.0f;
    #pragma unroll
    for (int i = 0; i < ROWS_PB * F4_ROW / THREADS; i++) {   // 16
        float4 v = xblk[tid + i * THREADS];
        s += (v.x + v.y) + (v.z + v.w);
    }
    #pragma unroll
    for (int off = 16; off > 0; off >>= 1)
        s += __shfl_down_sync(0xFFFFFFFFu, s, off);
    if (lid == 0) s_w[wid] = s;
    __syncthreads();
    if (tid == 0) {
        float t = (s_w[0] + s_w[1]) + (s_w[2] + s_w[3]);
        g_partials[b] = t;
        __threadfence();
        unsigned int tk = atomicAdd(&g_ticket, 1u);
        s_last = (tk == BLOCKS - 1);
    }
    __syncthreads();

    if (s_last) {   // block-uniform branch
        float a = 0.0f;
        #pragma unroll
        for (int i = 0; i < BLOCKS / THREADS; i++)          // fixed order
            a += g_partials[tid + i * THREADS];
        #pragma unroll
        for (int off = 16; off > 0; off >>= 1)
            a += __shfl_down_sync(0xFFFFFFFFu, a, off);
        if (lid == 0) s_w[wid] = a;
        __syncthreads();
        if (tid == 0) {
            float t = (s_w[0] + s_w[1]) + (s_w[2] + s_w[3]);
            g_mean  = t * (1.0f / (float)TOTAL);
            g_scale = 1.0f / (1.0f + expf(-wp[0]));
            g_ticket = 0;                  // reset for next graph replay
            __threadfence();
            *(volatile unsigned int*)&g_flag = epoch + 1;  // publish
        }
    }

    // ---- wait for mean ----
    if (tid == 0) {
        while (*(volatile unsigned int*)&g_flag == epoch) __nanosleep(64);
        s_ms[0] = *(volatile float*)&g_mean;
        s_ms[1] = *(volatile float*)&g_scale;
    }
    __syncthreads();
    float mean  = s_ms[0];
    float scale = s_ms[1];

    // ---- phase 2a: all 8 row norms, one barrier pair (data L1/L2-warm) ----
    float ss[ROWS_PB];
    #pragma unroll
    for (int r = 0; r < ROWS_PB; r++) {
        float acc = 0.0f;
        #pragma unroll
        for (int j = 0; j < F4_ROW / THREADS; j++) {        // 2
            float4 v = xblk[r * F4_ROW + j * THREADS + tid];
            float a0 = fmaxf(v.x - mean, 0.0f);
            float a1 = fmaxf(v.y - mean, 0.0f);
            float a2 = fmaxf(v.z - mean, 0.0f);
            float a3 = fmaxf(v.w - mean, 0.0f);
            acc += a0 * a0 + a1 * a1 + a2 * a2 + a3 * a3;
        }
        ss[r] = acc;
    }
    #pragma unroll
    for (int off = 16; off > 0; off >>= 1) {
        #pragma unroll
        for (int r = 0; r < ROWS_PB; r++)
            ss[r] += __shfl_down_sync(0xFFFFFFFFu, ss[r], off);
    }
    if (lid == 0) {
        #pragma unroll
        for (int r = 0; r < ROWS_PB; r++) s_ss[r][wid] = ss[r];
    }
    __syncthreads();
    if (tid < ROWS_PB) {
        float t = (s_ss[tid][0] + s_ss[tid][1]) + (s_ss[tid][2] + s_ss[tid][3]);
        s_inv[tid] = scale / fmaxf(sqrtf(t), 1e-12f);
    }
    __syncthreads();

    // ---- phase 2b: recompute (identical op order -> deterministic) + write
    float4* oblk = out4 + (long long)b * (ROWS_PB * NG * F4_ROW);
    #pragma unroll
    for (int r = 0; r < ROWS_PB; r++) {
        float inv = s_inv[r];
        float4* orow = oblk + r * (NG * F4_ROW);
        #pragma unroll
        for (int j = 0; j < F4_ROW / THREADS; j++) {
            float4 v = xblk[r * F4_ROW + j * THREADS + tid]; // L1 hit
            float4 o;
            o.x = fmaxf(v.x - mean, 0.0f) * inv;
            o.y = fmaxf(v.y - mean, 0.0f) * inv;
            o.z = fmaxf(v.z - mean, 0.0f) * inv;
            o.w = fmaxf(v.w - mean, 0.0f) * inv;
            #pragma unroll
            for (int g = 0; g < NG; g++)
                __stcs(&orow[g * F4_ROW + j * THREADS + tid], o);
        }
    }
}

// ---------------------------------------------------------------------------
extern "C" void kernel_launch(void* const* d_in, const int* in_sizes, int n_in,
                              void* d_out, int out_size) {
    const float4* xf = (const float4*)d_in[0];   // [8192, 1024] fp32
    const float*  wp = (const float*)d_in[1];    // [1] fp32
    // d_in[2] = W_tile — structurally kron(ones(1,G), eye(D)): unused.
    float4* out = (float4*)d_out;                // [8192, 8192] fp32

    k_fused<<<BLOCKS, THREADS>>>(xf, wp, out);
}